// round 12
// baseline (speedup 1.0000x reference)
#include <cuda_runtime.h>
#include <cuda_bf16.h>

#define N_NODES 50000
#define N_EDGES 800000
#define HID 64
#define IN_DIM 4
#define BN_EPS 1e-5f

#define SCAN_BLK 256
#define NBLK ((N_NODES + SCAN_BLK - 1) / SCAN_BLK)   // 196
static_assert(NBLK <= 256, "NBLK must fit one scan block");
static_assert(N_NODES < 65536, "src must fit in 16 bits");

// ---------------- scratch (static device globals; no allocation) ----------------
// Symbols passed as kernel args from host MUST be resolved with
// cudaGetSymbolAddress (bare symbol = host shadow; ATS silently reads host BSS).
__device__ __align__(16) int      g_deg[N_NODES];        // zeroed by fill_kernel for next replay
__device__ __align__(16) float    g_dinv[N_NODES];
__device__ __align__(16) int      g_rowptr[N_NODES + 1];
__device__ __align__(16) int      g_cursor[N_NODES];
__device__ __align__(16) unsigned g_sw[N_EDGES];         // src<<16 | bf16(w)
__device__ __align__(16) float    g_h[N_NODES * HID];    // fp32 residual stream
__device__ __align__(16) uint2    g_hwb[N_NODES * 16];   // bf16 message matrix: 16 x bf16x4 per row
__device__ __align__(16) int      g_blocksum[NBLK];
__device__ __align__(16) int      g_blockoff[NBLK];

// ---------------- graph preprocessing ----------------
__global__ void count_deg_kernel(const int* __restrict__ edge_index) {
    int e = blockIdx.x * blockDim.x + threadIdx.x;
    if (e < N_EDGES) {
        int dst = edge_index[N_EDGES + e];   // row 1 of [2, E]
        atomicAdd(&g_deg[dst], 1);
    }
}

// stage 1: per-block tree reduction of degrees (+ fused dinv computation)
__global__ void scan_reduce_kernel() {
    __shared__ int sdata[SCAN_BLK];
    int b = blockIdx.x, t = threadIdx.x;
    int i = b * SCAN_BLK + t;
    int d = (i < N_NODES) ? g_deg[i] : 0;
    if (i < N_NODES) g_dinv[i] = rsqrtf((float)(d + 1));  // +1 self loop
    sdata[t] = d;
    __syncthreads();
    #pragma unroll
    for (int s = SCAN_BLK / 2; s > 0; s >>= 1) {
        if (t < s) sdata[t] += sdata[t + s];
        __syncthreads();
    }
    if (t == 0) g_blocksum[b] = sdata[0];
}

// stage 2: one block scans the block sums (double-buffered)
__global__ void scan_offsets_kernel() {
    __shared__ int buf[2][256];
    int t = threadIdx.x;
    buf[0][t] = (t < NBLK) ? g_blocksum[t] : 0;
    int cur = 0;
    __syncthreads();
    #pragma unroll
    for (int off = 1; off < 256; off <<= 1) {
        int x = buf[cur][t];
        if (t >= off) x += buf[cur][t - off];
        buf[1 - cur][t] = x;
        cur = 1 - cur;
        __syncthreads();
    }
    if (t < NBLK) g_blockoff[t] = (t > 0) ? buf[cur][t - 1] : 0;
    if (t == NBLK - 1) g_rowptr[N_NODES] = buf[cur][t];
}

// stage 3: per-block scan of degrees + write rowptr/cursor
__global__ void scan_write_kernel() {
    __shared__ int buf[2][SCAN_BLK];
    int b = blockIdx.x, t = threadIdx.x;
    int i = b * SCAN_BLK + t;
    int v = (i < N_NODES) ? g_deg[i] : 0;
    buf[0][t] = v;
    int cur = 0;
    __syncthreads();
    #pragma unroll
    for (int off = 1; off < SCAN_BLK; off <<= 1) {
        int x = buf[cur][t];
        if (t >= off) x += buf[cur][t - off];
        buf[1 - cur][t] = x;
        cur = 1 - cur;
        __syncthreads();
    }
    int incl = buf[cur][t];
    int excl = incl - v + g_blockoff[b];
    if (i < N_NODES) {
        g_rowptr[i] = excl;
        g_cursor[i] = excl;
    }
}

// fill CSR; also re-zero g_deg for the next graph replay (deg is dead after scan_write)
__global__ void fill_kernel(const int* __restrict__ edge_index) {
    int e = blockIdx.x * blockDim.x + threadIdx.x;
    if (e < N_EDGES) {
        int src = edge_index[e];
        int dst = edge_index[N_EDGES + e];
        int pos = atomicAdd(&g_cursor[dst], 1);
        float w = g_dinv[src] * g_dinv[dst];
        unsigned short wb = __bfloat16_as_ushort(__float2bfloat16(w));
        g_sw[pos] = ((unsigned)src << 16) | (unsigned)wb;
    }
    if (e < N_NODES) g_deg[e] = 0;
}

// ---------------- input projection: h = x @ W_in + b_in ----------------
__global__ void in_proj_kernel(const float* __restrict__ x,
                               const float* __restrict__ W_in,
                               const float* __restrict__ b_in) {
    __shared__ float xs[64 * IN_DIM];
    __shared__ float Ws[IN_DIM * HID];
    __shared__ float bs[HID];
    int tid = threadIdx.x;
    int n0 = blockIdx.x * 64;

    if (tid < IN_DIM * HID) Ws[tid] = W_in[tid];
    if (tid < HID) bs[tid] = b_in[tid];
    {
        int node = n0 + (tid >> 2);
        xs[tid] = (node < N_NODES) ? x[n0 * IN_DIM + tid] : 0.f;
    }
    __syncthreads();

    int j = tid & 63;
    int ng = tid >> 6;
    float bj = bs[j];
    float w0 = Ws[0 * HID + j], w1 = Ws[1 * HID + j], w2 = Ws[2 * HID + j], w3 = Ws[3 * HID + j];
    #pragma unroll 4
    for (int nn = 0; nn < 16; nn++) {
        int nloc = ng * 16 + nn;
        int node = n0 + nloc;
        if (node < N_NODES) {
            const float* xr = &xs[nloc * IN_DIM];
            g_h[node * HID + j] = bj + xr[0] * w0 + xr[1] * w1 + xr[2] * w2 + xr[3] * w3;
        }
    }
}

// ---------------- 64x64 GEMM: hwb = bf16(A @ W) ----------------
// 128 nodes/block, 256 threads, each thread 8 nodes x 4 cols.
// A-tile cached in smem as bf16 -> 2x less crossbar traffic per FMA.
#define GT_NODES 128
#define HTB_STRIDE 136   // bf16 elems per k-row (128 + 8 pad), 272B, 16B-aligned
__global__ void gemm64_bf16_kernel(const float* __restrict__ A,
                                   const float* __restrict__ W,
                                   uint2* __restrict__ C) {
    __shared__ unsigned short hTb[64 * HTB_STRIDE];   // [k][node] bf16
    __shared__ float Ws[64 * 64];
    int tid = threadIdx.x;
    int n0 = blockIdx.x * GT_NODES;

    {
        const float4* W4 = (const float4*)W;
        float4* Ws4 = (float4*)Ws;
        #pragma unroll
        for (int i = tid; i < 1024; i += 256) Ws4[i] = W4[i];
    }
    {
        int nn = tid & 127;            // node within tile
        int kq0 = (tid >> 7) * 8;      // 0 or 8
        int node = n0 + nn;
        const float4* A4 = (const float4*)A;
        #pragma unroll
        for (int q = 0; q < 8; q++) {
            int kq = kq0 + q;          // 0..15 (4 k's each)
            float4 hv = (node < N_NODES) ? A4[node * 16 + kq]
                                         : make_float4(0.f, 0.f, 0.f, 0.f);
            hTb[(kq * 4 + 0) * HTB_STRIDE + nn] = __bfloat16_as_ushort(__float2bfloat16(hv.x));
            hTb[(kq * 4 + 1) * HTB_STRIDE + nn] = __bfloat16_as_ushort(__float2bfloat16(hv.y));
            hTb[(kq * 4 + 2) * HTB_STRIDE + nn] = __bfloat16_as_ushort(__float2bfloat16(hv.z));
            hTb[(kq * 4 + 3) * HTB_STRIDE + nn] = __bfloat16_as_ushort(__float2bfloat16(hv.w));
        }
    }
    __syncthreads();

    int nq = tid & 15;   // node octet: nodes nq*8 .. nq*8+7
    int jq = tid >> 4;   // col quad:  cols  jq*4 .. jq*4+3
    const float4* Ws4 = (const float4*)Ws;

    float4 acc[8];
    #pragma unroll
    for (int i = 0; i < 8; i++) acc[i] = make_float4(0.f, 0.f, 0.f, 0.f);

    #pragma unroll
    for (int k = 0; k < 64; k++) {
        float4 wv = Ws4[k * 16 + jq];
        uint4 hraw = *(const uint4*)&hTb[k * HTB_STRIDE + nq * 8];   // 8 bf16 = 8 nodes
        float2 f01 = __bfloat1622float2(*(__nv_bfloat162*)&hraw.x);
        float2 f23 = __bfloat1622float2(*(__nv_bfloat162*)&hraw.y);
        float2 f45 = __bfloat1622float2(*(__nv_bfloat162*)&hraw.z);
        float2 f67 = __bfloat1622float2(*(__nv_bfloat162*)&hraw.w);
        acc[0].x += f01.x * wv.x; acc[0].y += f01.x * wv.y; acc[0].z += f01.x * wv.z; acc[0].w += f01.x * wv.w;
        acc[1].x += f01.y * wv.x; acc[1].y += f01.y * wv.y; acc[1].z += f01.y * wv.z; acc[1].w += f01.y * wv.w;
        acc[2].x += f23.x * wv.x; acc[2].y += f23.x * wv.y; acc[2].z += f23.x * wv.z; acc[2].w += f23.x * wv.w;
        acc[3].x += f23.y * wv.x; acc[3].y += f23.y * wv.y; acc[3].z += f23.y * wv.z; acc[3].w += f23.y * wv.w;
        acc[4].x += f45.x * wv.x; acc[4].y += f45.x * wv.y; acc[4].z += f45.x * wv.z; acc[4].w += f45.x * wv.w;
        acc[5].x += f45.y * wv.x; acc[5].y += f45.y * wv.y; acc[5].z += f45.y * wv.z; acc[5].w += f45.y * wv.w;
        acc[6].x += f67.x * wv.x; acc[6].y += f67.x * wv.y; acc[6].z += f67.x * wv.z; acc[6].w += f67.x * wv.w;
        acc[7].x += f67.y * wv.x; acc[7].y += f67.y * wv.y; acc[7].z += f67.y * wv.z; acc[7].w += f67.y * wv.w;
    }

    #pragma unroll
    for (int ni = 0; ni < 8; ni++) {
        int node = n0 + nq * 8 + ni;
        if (node < N_NODES) {
            float4 r = acc[ni];
            __nv_bfloat162 lo = __floats2bfloat162_rn(r.x, r.y);
            __nv_bfloat162 hi = __floats2bfloat162_rn(r.z, r.w);
            uint2 pk;
            pk.x = *(unsigned int*)&lo;
            pk.y = *(unsigned int*)&hi;
            C[node * 16 + jq] = pk;   // row = 64 bf16 = 16 uint2
        }
    }
}

// ---------------- aggregate + BN + ReLU + residual ----------------
// 16-lane group per node; lane covers 4 features (bf16x4 = uint2 load).
// Packed edge word: src<<16 | bf16(w)  -> ONE shfl per edge.
__global__ void agg_kernel(const float* __restrict__ conv_b,
                           const float* __restrict__ bn_gamma,
                           const float* __restrict__ bn_beta,
                           const float* __restrict__ bn_mean,
                           const float* __restrict__ bn_var) {
    int gidx = (blockIdx.x * blockDim.x + threadIdx.x) >> 4;   // group = node
    int gl = threadIdx.x & 15;                                  // lane in group
    if (gidx >= N_NODES) return;
    int v = gidx;
    unsigned gmask = 0xFFFFu << (threadIdx.x & 16);             // this half-warp

    float4* h4 = (float4*)g_h;

    float dv = g_dinv[v];
    float wself = dv * dv;
    float4 acc;
    {
        uint2 pk = g_hwb[v * 16 + gl];
        float2 lo = __bfloat1622float2(*(__nv_bfloat162*)&pk.x);
        float2 hi = __bfloat1622float2(*(__nv_bfloat162*)&pk.y);
        acc.x = lo.x * wself; acc.y = lo.y * wself;
        acc.z = hi.x * wself; acc.w = hi.y * wself;
    }

    int beg = g_rowptr[v];
    int end = g_rowptr[v + 1];
    int e = beg;
    // full tiles of 16 edges: fixed trip count -> unrolled, loads batched
    for (; e + 16 <= end; e += 16) {
        unsigned p = g_sw[e + gl];
        #pragma unroll
        for (int j = 0; j < 16; j++) {
            unsigned u = __shfl_sync(gmask, p, j, 16);
            int s = (int)(u >> 16);
            float w = __bfloat162float(__ushort_as_bfloat16((unsigned short)(u & 0xFFFFu)));
            uint2 pk = g_hwb[s * 16 + gl];
            float2 lo = __bfloat1622float2(*(__nv_bfloat162*)&pk.x);
            float2 hi = __bfloat1622float2(*(__nv_bfloat162*)&pk.y);
            acc.x += lo.x * w; acc.y += lo.y * w;
            acc.z += hi.x * w; acc.w += hi.y * w;
        }
    }
    // remainder
    if (e < end) {
        int idx = e + gl;
        unsigned p = (idx < end) ? g_sw[idx] : 0u;
        int cnt = end - e;
        for (int j = 0; j < cnt; j++) {
            unsigned u = __shfl_sync(gmask, p, j, 16);
            int s = (int)(u >> 16);
            float w = __bfloat162float(__ushort_as_bfloat16((unsigned short)(u & 0xFFFFu)));
            uint2 pk = g_hwb[s * 16 + gl];
            float2 lo = __bfloat1622float2(*(__nv_bfloat162*)&pk.x);
            float2 hi = __bfloat1622float2(*(__nv_bfloat162*)&pk.y);
            acc.x += lo.x * w; acc.y += lo.y * w;
            acc.z += hi.x * w; acc.w += hi.y * w;
        }
    }

    // fused epilogue: + conv_b, BN(eval), ReLU, + residual
    float4 cb = ((const float4*)conv_b)[gl];
    float4 gm = ((const float4*)bn_gamma)[gl];
    float4 bt = ((const float4*)bn_beta)[gl];
    float4 mn = ((const float4*)bn_mean)[gl];
    float4 vr = ((const float4*)bn_var)[gl];
    float4 o;
    o.x = fmaxf((acc.x + cb.x - mn.x) * (gm.x * rsqrtf(vr.x + BN_EPS)) + bt.x, 0.f);
    o.y = fmaxf((acc.y + cb.y - mn.y) * (gm.y * rsqrtf(vr.y + BN_EPS)) + bt.y, 0.f);
    o.z = fmaxf((acc.z + cb.z - mn.z) * (gm.z * rsqrtf(vr.z + BN_EPS)) + bt.z, 0.f);
    o.w = fmaxf((acc.w + cb.w - mn.w) * (gm.w * rsqrtf(vr.w + BN_EPS)) + bt.w, 0.f);
    float4 res = h4[v * 16 + gl];
    o.x += res.x; o.y += res.y; o.z += res.z; o.w += res.w;
    h4[v * 16 + gl] = o;
}

// ---------------- fused output MLP: out = x + relu(h@W1+b1)@W2 + b2 ----------------
__global__ void out_fused_kernel(const float* __restrict__ A,   // g_h (device ptr)
                                 const float* __restrict__ W1,
                                 const float* __restrict__ b1,
                                 const float* __restrict__ W2,
                                 const float* __restrict__ b2,
                                 const float* __restrict__ x,
                                 float* __restrict__ out) {
    __shared__ float hT[64 * 68];
    __shared__ float Ws[64 * 64];
    __shared__ float ts[64 * 68];
    __shared__ float W2s[HID * IN_DIM];
    __shared__ float b2s[IN_DIM];
    int tid = threadIdx.x;
    int n0 = blockIdx.x * 64;

    {
        const float4* W4 = (const float4*)W1;
        float4* Ws4 = (float4*)Ws;
        #pragma unroll
        for (int i = tid; i < 1024; i += 256) Ws4[i] = W4[i];
    }
    if (tid < HID * IN_DIM) W2s[tid] = W2[tid];
    if (tid < IN_DIM) b2s[tid] = b2[tid];
    {
        int nn = tid & 63;
        int kq4 = tid >> 6;
        int node = n0 + nn;
        const float4* A4 = (const float4*)A;
        #pragma unroll
        for (int q = 0; q < 4; q++) {
            int kq = kq4 * 4 + q;
            float4 hv = (node < N_NODES) ? A4[node * 16 + kq]
                                         : make_float4(0.f, 0.f, 0.f, 0.f);
            hT[(kq * 4 + 0) * 68 + nn] = hv.x;
            hT[(kq * 4 + 1) * 68 + nn] = hv.y;
            hT[(kq * 4 + 2) * 68 + nn] = hv.z;
            hT[(kq * 4 + 3) * 68 + nn] = hv.w;
        }
    }
    __syncthreads();

    int nq = tid & 15;
    int jq = tid >> 4;
    const float4* Ws4 = (const float4*)Ws;

    float4 acc0 = make_float4(0.f, 0.f, 0.f, 0.f);
    float4 acc1 = acc0, acc2 = acc0, acc3 = acc0;
    #pragma unroll
    for (int k = 0; k < 64; k++) {
        float4 wv = Ws4[k * 16 + jq];
        float4 hv = *(const float4*)&hT[k * 68 + nq * 4];
        acc0.x += hv.x * wv.x; acc0.y += hv.x * wv.y; acc0.z += hv.x * wv.z; acc0.w += hv.x * wv.w;
        acc1.x += hv.y * wv.x; acc1.y += hv.y * wv.y; acc1.z += hv.y * wv.z; acc1.w += hv.y * wv.w;
        acc2.x += hv.z * wv.x; acc2.y += hv.z * wv.y; acc2.z += hv.z * wv.z; acc2.w += hv.z * wv.w;
        acc3.x += hv.w * wv.x; acc3.y += hv.w * wv.y; acc3.z += hv.w * wv.z; acc3.w += hv.w * wv.w;
    }

    float4 bv = ((const float4*)b1)[jq];
    float4 accs[4] = {acc0, acc1, acc2, acc3};
    #pragma unroll
    for (int ni = 0; ni < 4; ni++) {
        int nloc = nq * 4 + ni;
        float4 r = accs[ni];
        r.x = fmaxf(r.x + bv.x, 0.f);
        r.y = fmaxf(r.y + bv.y, 0.f);
        r.z = fmaxf(r.z + bv.z, 0.f);
        r.w = fmaxf(r.w + bv.w, 0.f);
        *(float4*)&ts[nloc * 68 + jq * 4] = r;
    }
    __syncthreads();

    int nloc = tid >> 2;
    int m = tid & 3;
    int node = n0 + nloc;
    float acc = 0.f;
    #pragma unroll
    for (int l = 0; l < 64; l++) {
        acc += ts[nloc * 68 + l] * W2s[l * IN_DIM + m];
    }
    if (node < N_NODES) {
        out[node * IN_DIM + m] = x[node * IN_DIM + m] + b2s[m] + acc;
    }
}

// ---------------- launch ----------------
extern "C" void kernel_launch(void* const* d_in, const int* in_sizes, int n_in,
                              void* d_out, int out_size) {
    const float* x          = (const float*)d_in[0];
    const int*   edge_index = (const int*)d_in[1];
    const float* W_in       = (const float*)d_in[2];
    const float* b_in       = (const float*)d_in[3];
    const float* conv_w     = (const float*)d_in[4];   // [3,64,64]
    const float* conv_b     = (const float*)d_in[5];   // [3,64]
    const float* bn_gamma   = (const float*)d_in[6];
    const float* bn_beta    = (const float*)d_in[7];
    const float* bn_mean    = (const float*)d_in[8];
    const float* bn_var     = (const float*)d_in[9];
    const float* W1         = (const float*)d_in[10];
    const float* b1         = (const float*)d_in[11];
    const float* W2         = (const float*)d_in[12];
    const float* b2         = (const float*)d_in[13];
    float* out = (float*)d_out;

    void* p_h = nullptr;
    void* p_hwb = nullptr;
    cudaGetSymbolAddress(&p_h, g_h);
    cudaGetSymbolAddress(&p_hwb, g_hwb);
    float* d_h = (float*)p_h;
    uint2* d_hwb = (uint2*)p_hwb;

    const int TPB = 256;
    const int gridE  = (N_EDGES + TPB - 1) / TPB;
    const int gridT  = (N_NODES + 63) / 64;               // 64-node tiles (in_proj, out_fused)
    const int gridT2 = (N_NODES + GT_NODES - 1) / GT_NODES; // 128-node tiles (gemm)
    const int gridG  = (N_NODES * 16 + TPB - 1) / TPB;    // 16-lane group per node

    // Launch order puts gemm1 at index 3 so the fixed ncu window profiles it.
    in_proj_kernel<<<gridT, TPB>>>(x, W_in, b_in);                        // 0
    count_deg_kernel<<<gridE, TPB>>>(edge_index);                         // 1
    scan_reduce_kernel<<<NBLK, SCAN_BLK>>>();                             // 2 (also dinv)
    gemm64_bf16_kernel<<<gridT2, TPB>>>(d_h, conv_w + 0 * HID * HID, d_hwb); // 3  <- profiled
    scan_offsets_kernel<<<1, 256>>>();                                    // 4
    scan_write_kernel<<<NBLK, SCAN_BLK>>>();                              // 5
    fill_kernel<<<gridE, TPB>>>(edge_index);                              // 6 (also re-zeros deg)

    // layer 1 aggregate
    agg_kernel<<<gridG, TPB>>>(conv_b + 0 * HID,
                               bn_gamma + 0 * HID, bn_beta + 0 * HID,
                               bn_mean + 0 * HID, bn_var + 0 * HID);      // 7

    // layers 2..3
    for (int i = 1; i < 3; i++) {
        gemm64_bf16_kernel<<<gridT2, TPB>>>(d_h, conv_w + i * HID * HID, d_hwb);
        agg_kernel<<<gridG, TPB>>>(conv_b + i * HID,
                                   bn_gamma + i * HID, bn_beta + i * HID,
                                   bn_mean + i * HID, bn_var + i * HID);
    }

    // fused output MLP + residual
    out_fused_kernel<<<gridT, TPB>>>(d_h, W1, b1, W2, b2, x, out);
}